// round 3
// baseline (speedup 1.0000x reference)
#include <cuda_runtime.h>
#include <cstdint>

#define DIMV   512
#define NTOK   256
#define NKEEP  128
#define HID    102
#define KP     51
#define OUTROWS 52

typedef unsigned long long ull;

struct __align__(16) Smem {
    union {
        float scratch[8 * 512];                       // phase-1 column partials (16 KB)
        struct { float A[128 * 72]; float Bt[64 * 104]; } g1;  // GEMM1 tiles (63.5 KB)
        float H[128 * 104];                           // H rows; cols 52..103 reused for w (53.2 KB)
    } u;
    float W2s[HID * 52];    // W2 padded, col 51 = 0
    float g[512];
    float bln[512];
    float glo[512];
    float rowsum[256];
    float rowsumsq[256];
    float score[256];
    float nscore[128];
    float nw[128];
    float mu[128];
    float rinv[128];
    float b1p[104];
    float b2s[52];
    int   selidx[128];
    int   nonidx[128];
    float red[8];
    float ssq;
};

__device__ __forceinline__ ull ffma2(ull a, ull b, ull c) {
    ull d;
    asm("fma.rn.f32x2 %0, %1, %2, %3;" : "=l"(d) : "l"(a), "l"(b), "l"(c));
    return d;
}
__device__ __forceinline__ ull pack2(float x, float y) {
    ull d;
    asm("mov.b64 %0, {%1, %2};" : "=l"(d) : "f"(x), "f"(y));
    return d;
}
__device__ __forceinline__ float2 unpack2(ull v) {
    float2 r;
    asm("mov.b64 {%0, %1}, %2;" : "=f"(r.x), "=f"(r.y) : "l"(v));
    return r;
}
__device__ __forceinline__ float gelu_exact(float v) {
    return 0.5f * v * (1.0f + erff(v * 0.70710678118654752f));
}

__global__ __launch_bounds__(256, 2)
void ATRM_73581379715509_kernel(
    const float* __restrict__ x, const float* __restrict__ ca,
    const float* __restrict__ lng, const float* __restrict__ lnb,
    const float* __restrict__ W1, const float* __restrict__ b1,
    const float* __restrict__ W2, const float* __restrict__ b2,
    const float* __restrict__ scale, float* __restrict__ out)
{
    extern __shared__ char smem_raw[];
    Smem& s = *reinterpret_cast<Smem*>(smem_raw);

    const int b    = blockIdx.x;
    const int tid  = threadIdx.x;
    const int warp = tid >> 5;
    const int lane = tid & 31;
    const float* __restrict__ xb = x + (size_t)b * NTOK * DIMV;
    float* __restrict__ ob = out + (size_t)b * OUTROWS * DIMV;

    // ---- constant loads + pads (regions disjoint from phase-1 scratch) ----
    s.g[tid]         = lng[tid];
    s.g[tid + 256]   = lng[tid + 256];
    s.bln[tid]       = lnb[tid];
    s.bln[tid + 256] = lnb[tid + 256];
    if (tid < 104) s.b1p[tid] = (tid < HID) ? b1[tid] : 0.0f;
    if (tid < KP)  s.b2s[tid] = b2[tid];
    if (tid < 128) s.u.g1.Bt[(tid >> 1) * 104 + 102 + (tid & 1)] = 0.0f;  // Bt pad cols (beyond scratch)
    if (tid < HID) s.W2s[tid * 52 + 51] = 0.0f;                           // W2 pad col
    #pragma unroll
    for (int j = tid; j < HID * KP; j += 256)
        s.W2s[(j / KP) * 52 + (j % KP)] = W2[j];

    // ---- PHASE 1: rowsum/rowsumsq + per-warp column partials (32 rows/warp) ----
    float4 cs0 = make_float4(0,0,0,0), cs1 = cs0, cs2 = cs0, cs3 = cs0;
    #pragma unroll 1
    for (int r = 0; r < 32; r++) {
        const int t = warp * 32 + r;
        const float4* row = reinterpret_cast<const float4*>(xb + t * DIMV);
        float4 v0 = row[lane], v1 = row[lane + 32], v2 = row[lane + 64], v3 = row[lane + 96];
        float rs = v0.x+v0.y+v0.z+v0.w + v1.x+v1.y+v1.z+v1.w
                 + v2.x+v2.y+v2.z+v2.w + v3.x+v3.y+v3.z+v3.w;
        float rq = v0.x*v0.x+v0.y*v0.y+v0.z*v0.z+v0.w*v0.w
                 + v1.x*v1.x+v1.y*v1.y+v1.z*v1.z+v1.w*v1.w
                 + v2.x*v2.x+v2.y*v2.y+v2.z*v2.z+v2.w*v2.w
                 + v3.x*v3.x+v3.y*v3.y+v3.z*v3.z+v3.w*v3.w;
        cs0.x += v0.x; cs0.y += v0.y; cs0.z += v0.z; cs0.w += v0.w;
        cs1.x += v1.x; cs1.y += v1.y; cs1.z += v1.z; cs1.w += v1.w;
        cs2.x += v2.x; cs2.y += v2.y; cs2.z += v2.z; cs2.w += v2.w;
        cs3.x += v3.x; cs3.y += v3.y; cs3.z += v3.z; cs3.w += v3.w;
        #pragma unroll
        for (int off = 16; off; off >>= 1) {
            rs += __shfl_down_sync(0xffffffffu, rs, off);
            rq += __shfl_down_sync(0xffffffffu, rq, off);
        }
        if (lane == 0) { s.rowsum[t] = rs; s.rowsumsq[t] = rq; }
    }
    {
        float4* cp = reinterpret_cast<float4*>(s.u.scratch + warp * 512);
        cp[lane] = cs0; cp[lane + 32] = cs1; cp[lane + 64] = cs2; cp[lane + 96] = cs3;
    }
    __syncthreads();

    // deterministic column reduction: each thread owns cols tid and tid+256
    float cacc1 = 0.0f, cacc2 = 0.0f;
    #pragma unroll
    for (int w0 = 0; w0 < 8; w0++) {
        cacc1 += s.u.scratch[w0 * 512 + tid];
        cacc2 += s.u.scratch[w0 * 512 + tid + 256];
    }
    {
        float p = cacc1 * cacc1 + cacc2 * cacc2;
        #pragma unroll
        for (int off = 16; off; off >>= 1) p += __shfl_down_sync(0xffffffffu, p, off);
        if (lane == 0) s.red[warp] = p;
    }
    __syncthreads();
    if (tid == 0) {
        float t = 0.0f;
        #pragma unroll
        for (int i = 0; i < 8; i++) t += s.red[i];
        s.ssq = t;
    }
    __syncthreads();
    {
        const float inv = 1.0f / fmaxf(sqrtf(s.ssq), 2.56e-10f);  // glo = colsum / max(||colsum||, 256e-12)
        s.glo[tid]       = cacc1 * inv;
        s.glo[tid + 256] = cacc2 * inv;
    }
    __syncthreads();

    // ---- PHASE 2: scores ----
    {
        const float4* glo4 = reinterpret_cast<const float4*>(s.glo);
        #pragma unroll 1
        for (int r = 0; r < 32; r++) {
            const int t = warp * 32 + r;
            const float4* row = reinterpret_cast<const float4*>(xb + t * DIMV);
            float d = 0.0f;
            #pragma unroll
            for (int q = 0; q < 4; q++) {
                float4 v = row[lane + 32 * q];
                float4 gg = glo4[lane + 32 * q];
                d += v.x * gg.x + v.y * gg.y + v.z * gg.z + v.w * gg.w;
            }
            #pragma unroll
            for (int off = 16; off; off >>= 1) d += __shfl_down_sync(0xffffffffu, d, off);
            if (lane == 0) {
                float nr = sqrtf(s.rowsumsq[t]);
                s.score[t] = d / fmaxf(nr, 1e-12f) + ca[(size_t)b * NTOK + t];
            }
        }
    }
    __syncthreads();

    // ---- PHASE 3: rank partition (matches stable argsort of -score) ----
    {
        const float sc = s.score[tid];
        int rank = 0;
        #pragma unroll 4
        for (int j = 0; j < NTOK; j++) {
            float sj = s.score[j];
            rank += (sj > sc) || (sj == sc && j < tid);
        }
        const float mu  = s.rowsum[tid] * (1.0f / 512.0f);
        const float var = s.rowsumsq[tid] * (1.0f / 512.0f) - mu * mu;
        if (rank < NKEEP) {
            s.selidx[rank] = tid;
            s.mu[rank]     = mu;
            s.rinv[rank]   = rsqrtf(var + 1e-5f);
        } else {
            s.nonidx[rank - NKEEP] = tid;
            s.nscore[rank - NKEEP] = sc;
        }
    }
    __syncthreads();

    // ---- PHASE 4: softmax over non-kept scores (warp 0) ----
    if (warp == 0) {
        float v0 = s.nscore[lane], v1 = s.nscore[lane + 32],
              v2 = s.nscore[lane + 64], v3 = s.nscore[lane + 96];
        float m = fmaxf(fmaxf(v0, v1), fmaxf(v2, v3));
        #pragma unroll
        for (int off = 16; off; off >>= 1) m = fmaxf(m, __shfl_xor_sync(0xffffffffu, m, off));
        float e0 = expf(v0 - m), e1 = expf(v1 - m), e2 = expf(v2 - m), e3 = expf(v3 - m);
        float su = e0 + e1 + e2 + e3;
        #pragma unroll
        for (int off = 16; off; off >>= 1) su += __shfl_xor_sync(0xffffffffu, su, off);
        const float inv = 1.0f / su;
        s.nw[lane] = e0 * inv; s.nw[lane + 32] = e1 * inv;
        s.nw[lane + 64] = e2 * inv; s.nw[lane + 96] = e3 * inv;
    }
    __syncthreads();

    // ---- PHASE 5: extra row (out row 51), 2 cols/thread, depth-2 prefetch ----
    {
        float acc1 = 0.0f, acc2 = 0.0f;
        int i0 = s.nonidx[0], i1 = s.nonidx[1];
        float a0 = xb[(size_t)i0 * DIMV + tid],       b0 = xb[(size_t)i0 * DIMV + tid + 256];
        float a1 = xb[(size_t)i1 * DIMV + tid],       b1v = xb[(size_t)i1 * DIMV + tid + 256];
        #pragma unroll 2
        for (int k = 0; k < 128; k++) {
            float an = 0.0f, bn = 0.0f;
            if (k + 2 < 128) {
                int in = s.nonidx[k + 2];
                an = xb[(size_t)in * DIMV + tid];
                bn = xb[(size_t)in * DIMV + tid + 256];
            }
            float w = s.nw[k];
            acc1 += w * a0; acc2 += w * b0;
            a0 = a1; b0 = b1v; a1 = an; b1v = bn;
        }
        ob[51 * DIMV + tid]       = acc1;
        ob[51 * DIMV + tid + 256] = acc2;
    }

    // ---- GEMM1: H = gelu( LN(sel) @ W1 + b1 ), full-K accumulators ----
    const bool act = (tid < 208);
    const int  mt  = tid / 13, nt = tid % 13;
    const int  m0  = mt * 8,  n0 = nt * 8;

    ull acc[8][4];
    #pragma unroll
    for (int i = 0; i < 8; i++)
        #pragma unroll
        for (int j = 0; j < 4; j++) acc[i][j] = 0ull;

    #pragma unroll 1
    for (int kt = 0; kt < 8; kt++) {
        const int d0 = kt * 64;
        // fill A (LN applied), layout [t][72]
        #pragma unroll
        for (int j = tid; j < 2048; j += 256) {
            const int t  = j >> 4;
            const int dv = (j & 15) << 2;
            const int rowi = s.selidx[t];
            float4 v = *reinterpret_cast<const float4*>(xb + (size_t)rowi * DIMV + d0 + dv);
            const float muv = s.mu[t], ri = s.rinv[t];
            const int dd = d0 + dv;
            float4 y;
            y.x = (v.x - muv) * ri * s.g[dd + 0] + s.bln[dd + 0];
            y.y = (v.y - muv) * ri * s.g[dd + 1] + s.bln[dd + 1];
            y.z = (v.z - muv) * ri * s.g[dd + 2] + s.bln[dd + 2];
            y.w = (v.w - muv) * ri * s.g[dd + 3] + s.bln[dd + 3];
            *reinterpret_cast<float4*>(&s.u.g1.A[t * 72 + dv]) = y;
        }
        // fill Bt = W1 tile via float2, layout [dk][104] (cols 102/103 stay 0)
        #pragma unroll
        for (int jj = tid; jj < 64 * 51; jj += 256) {
            const int dk = jj / 51;
            const int c2 = jj - dk * 51;
            float2 v = *reinterpret_cast<const float2*>(W1 + (size_t)(d0 + dk) * HID + 2 * c2);
            *reinterpret_cast<float2*>(&s.u.g1.Bt[dk * 104 + 2 * c2]) = v;
        }
        __syncthreads();
        if (act) {
            const float* Abase = s.u.g1.A + m0 * 72;
            const float* Bbase = s.u.g1.Bt + n0;
            #pragma unroll 2
            for (int dk = 0; dk < 64; dk++) {
                ull a2[8];
                #pragma unroll
                for (int i = 0; i < 8; i++) {
                    float av = Abase[i * 72 + dk];
                    a2[i] = pack2(av, av);
                }
                const ull* bp = reinterpret_cast<const ull*>(Bbase + (size_t)dk * 104);
                ull b2v[4];
                #pragma unroll
                for (int j = 0; j < 4; j++) b2v[j] = bp[j];
                #pragma unroll
                for (int i = 0; i < 8; i++)
                    #pragma unroll
                    for (int j = 0; j < 4; j++)
                        acc[i][j] = ffma2(a2[i], b2v[j], acc[i][j]);
            }
        }
        __syncthreads();
    }
    // write H = gelu(acc + b1) into union (overlaps dead A/Bt)
    if (act) {
        #pragma unroll
        for (int i = 0; i < 8; i++) {
            #pragma unroll
            for (int j = 0; j < 4; j++) {
                float2 p = unpack2(acc[i][j]);
                const int n = n0 + 2 * j;
                float v0 = gelu_exact(p.x + s.b1p[n]);
                float v1 = gelu_exact(p.y + s.b1p[n + 1]);
                *reinterpret_cast<float2*>(&s.u.H[(m0 + i) * 104 + n]) = make_float2(v0, v1);
            }
        }
    }
    __syncthreads();

    // ---- GEMM2: w = (H @ W2 + b2) * scale, written into H[t][52..103] ----
    {
        const int t  = tid >> 1;
        const int c0 = (tid & 1) * 26;
        ull accw[13];
        #pragma unroll
        for (int i = 0; i < 13; i++) accw[i] = 0ull;
        const float* hrow = &s.u.H[t * 104];
        #pragma unroll 2
        for (int k = 0; k < HID; k++) {
            const float h = hrow[k];
            const ull h2 = pack2(h, h);
            const ull* wr = reinterpret_cast<const ull*>(&s.W2s[k * 52 + c0]);
            #pragma unroll
            for (int i = 0; i < 13; i++) accw[i] = ffma2(h2, wr[i], accw[i]);
        }
        const float sv = scale[0];
        __syncwarp();  // partner thread (same warp) must finish reading hrow before we overwrite cols 52+
        float* wrow = &s.u.H[t * 104 + 52];
        #pragma unroll
        for (int i = 0; i < 13; i++) {
            float2 v = unpack2(accw[i]);
            const int c = c0 + 2 * i;
            float o0 = (v.x + s.b2s[c]) * sv;
            float o1 = (c + 1 < KP) ? (v.y + s.b2s[c + 1]) * sv : 0.0f;  // col 51 -> 0
            *reinterpret_cast<float2*>(&wrow[c]) = make_float2(o0, o1);
        }
    }
    __syncthreads();

    // ---- softmax over 128 tokens per weight column (w lives at H[t][52+c]) ----
    for (int c = warp; c < KP; c += 8) {
        const int base = 52 + c;
        float v0 = s.u.H[(lane) * 104 + base],      v1 = s.u.H[(lane + 32) * 104 + base],
              v2 = s.u.H[(lane + 64) * 104 + base], v3 = s.u.H[(lane + 96) * 104 + base];
        float m = fmaxf(fmaxf(v0, v1), fmaxf(v2, v3));
        #pragma unroll
        for (int off = 16; off; off >>= 1) m = fmaxf(m, __shfl_xor_sync(0xffffffffu, m, off));
        float e0 = expf(v0 - m), e1 = expf(v1 - m), e2 = expf(v2 - m), e3 = expf(v3 - m);
        float su = e0 + e1 + e2 + e3;
        #pragma unroll
        for (int off = 16; off; off >>= 1) su += __shfl_xor_sync(0xffffffffu, su, off);
        const float inv = 1.0f / su;
        s.u.H[(lane) * 104 + base]      = e0 * inv;
        s.u.H[(lane + 32) * 104 + base] = e1 * inv;
        s.u.H[(lane + 64) * 104 + base] = e2 * inv;
        s.u.H[(lane + 96) * 104 + base] = e3 * inv;
    }
    __syncthreads();

    // ---- aggr: out[p][c] = sum_k w[k][p] * sel[k][c]; two passes of 256 cols ----
    #pragma unroll 1
    for (int pass = 0; pass < 2; pass++) {
        const int c = tid + pass * 256;
        ull acc2[26];
        #pragma unroll
        for (int p = 0; p < 26; p++) acc2[p] = 0ull;
        float xv0 = xb[(size_t)s.selidx[0] * DIMV + c];
        float xv1 = xb[(size_t)s.selidx[1] * DIMV + c];
        #pragma unroll 2
        for (int k = 0; k < 128; k++) {
            float nxt = (k + 2 < 128) ? xb[(size_t)s.selidx[k + 2] * DIMV + c] : 0.0f;
            const ull x2 = pack2(xv0, xv0);
            const ull* wr = reinterpret_cast<const ull*>(&s.u.H[k * 104 + 52]);
            #pragma unroll
            for (int p = 0; p < 26; p++) acc2[p] = ffma2(x2, wr[p], acc2[p]);
            xv0 = xv1; xv1 = nxt;
        }
        #pragma unroll
        for (int p = 0; p < 26; p++) {
            float2 v = unpack2(acc2[p]);
            ob[(2 * p) * DIMV + c] = v.x;
            if (2 * p + 1 < KP) ob[(2 * p + 1) * DIMV + c] = v.y;
        }
    }
}

extern "C" void kernel_launch(void* const* d_in, const int* in_sizes, int n_in,
                              void* d_out, int out_size) {
    (void)in_sizes; (void)n_in; (void)out_size;
    const float* x    = (const float*)d_in[0];
    const float* ca   = (const float*)d_in[1];
    const float* lng  = (const float*)d_in[2];
    const float* lnb  = (const float*)d_in[3];
    const float* W1   = (const float*)d_in[4];
    const float* b1   = (const float*)d_in[5];
    const float* W2   = (const float*)d_in[6];
    const float* b2   = (const float*)d_in[7];
    const float* sc   = (const float*)d_in[8];
    float* out = (float*)d_out;

    static_assert(sizeof(Smem) <= 110 * 1024, "smem too big for 2 CTAs/SM");
    cudaFuncSetAttribute(ATRM_73581379715509_kernel,
                         cudaFuncAttributeMaxDynamicSharedMemorySize,
                         (int)sizeof(Smem));
    ATRM_73581379715509_kernel<<<512, 256, sizeof(Smem)>>>(
        x, ca, lng, lnb, W1, b1, W2, b2, sc, out);
}

// round 4
// speedup vs baseline: 1.2615x; 1.2615x over previous
#include <cuda_runtime.h>
#include <cstdint>

#define DIMV   512
#define NTOK   256
#define NKEEP  128
#define HID    102
#define KP     51
#define OUTROWS 52
#define NB     512

typedef unsigned long long ull;

// ---------------- global scratch (allowed: __device__ arrays) ----------------
__device__ float g_glo[NB * DIMV];
__device__ float g_rowsum[NB * NTOK];
__device__ float g_rowsumsq[NB * NTOK];
__device__ int   g_selidx[NB * NKEEP];
__device__ float g_mu[NB * NKEEP];
__device__ float g_rinv[NB * NKEEP];

__device__ __forceinline__ ull ffma2(ull a, ull b, ull c) {
    ull d;
    asm("fma.rn.f32x2 %0, %1, %2, %3;" : "=l"(d) : "l"(a), "l"(b), "l"(c));
    return d;
}
__device__ __forceinline__ ull pack2(float x, float y) {
    ull d;
    asm("mov.b64 %0, {%1, %2};" : "=l"(d) : "f"(x), "f"(y));
    return d;
}
__device__ __forceinline__ float2 unpack2(ull v) {
    float2 r;
    asm("mov.b64 {%0, %1}, %2;" : "=f"(r.x), "=f"(r.y) : "l"(v));
    return r;
}
__device__ __forceinline__ float gelu_exact(float v) {
    return 0.5f * v * (1.0f + erff(v * 0.70710678118654752f));
}

// =====================================================================
// K1: per-batch stats — rowsum, rowsumsq, glo (normalized column mean)
// =====================================================================
__global__ __launch_bounds__(256)
void k1_stats(const float* __restrict__ x)
{
    __shared__ float scratch[8 * 512];
    __shared__ float red[8];
    __shared__ float ssq;

    const int b    = blockIdx.x;
    const int tid  = threadIdx.x;
    const int warp = tid >> 5;
    const int lane = tid & 31;
    const float* __restrict__ xb = x + (size_t)b * NTOK * DIMV;

    float4 cs0 = make_float4(0,0,0,0), cs1 = cs0, cs2 = cs0, cs3 = cs0;
    #pragma unroll 1
    for (int r = 0; r < 32; r++) {
        const int t = warp * 32 + r;
        const float4* row = reinterpret_cast<const float4*>(xb + t * DIMV);
        float4 v0 = row[lane], v1 = row[lane + 32], v2 = row[lane + 64], v3 = row[lane + 96];
        float rs = v0.x+v0.y+v0.z+v0.w + v1.x+v1.y+v1.z+v1.w
                 + v2.x+v2.y+v2.z+v2.w + v3.x+v3.y+v3.z+v3.w;
        float rq = v0.x*v0.x+v0.y*v0.y+v0.z*v0.z+v0.w*v0.w
                 + v1.x*v1.x+v1.y*v1.y+v1.z*v1.z+v1.w*v1.w
                 + v2.x*v2.x+v2.y*v2.y+v2.z*v2.z+v2.w*v2.w
                 + v3.x*v3.x+v3.y*v3.y+v3.z*v3.z+v3.w*v3.w;
        cs0.x += v0.x; cs0.y += v0.y; cs0.z += v0.z; cs0.w += v0.w;
        cs1.x += v1.x; cs1.y += v1.y; cs1.z += v1.z; cs1.w += v1.w;
        cs2.x += v2.x; cs2.y += v2.y; cs2.z += v2.z; cs2.w += v2.w;
        cs3.x += v3.x; cs3.y += v3.y; cs3.z += v3.z; cs3.w += v3.w;
        #pragma unroll
        for (int off = 16; off; off >>= 1) {
            rs += __shfl_down_sync(0xffffffffu, rs, off);
            rq += __shfl_down_sync(0xffffffffu, rq, off);
        }
        if (lane == 0) {
            g_rowsum[b * NTOK + t]   = rs;
            g_rowsumsq[b * NTOK + t] = rq;
        }
    }
    {
        float4* cp = reinterpret_cast<float4*>(scratch + warp * 512);
        cp[lane] = cs0; cp[lane + 32] = cs1; cp[lane + 64] = cs2; cp[lane + 96] = cs3;
    }
    __syncthreads();

    float cacc1 = 0.0f, cacc2 = 0.0f;
    #pragma unroll
    for (int w0 = 0; w0 < 8; w0++) {
        cacc1 += scratch[w0 * 512 + tid];
        cacc2 += scratch[w0 * 512 + tid + 256];
    }
    {
        float p = cacc1 * cacc1 + cacc2 * cacc2;
        #pragma unroll
        for (int off = 16; off; off >>= 1) p += __shfl_down_sync(0xffffffffu, p, off);
        if (lane == 0) red[warp] = p;
    }
    __syncthreads();
    if (tid == 0) {
        float t = 0.0f;
        #pragma unroll
        for (int i = 0; i < 8; i++) t += red[i];
        ssq = t;
    }
    __syncthreads();
    {
        const float inv = 1.0f / fmaxf(sqrtf(ssq), 2.56e-10f);
        g_glo[b * DIMV + tid]       = cacc1 * inv;
        g_glo[b * DIMV + tid + 256] = cacc2 * inv;
    }
}

// =====================================================================
// K2: scores, rank partition, non-kept softmax, extra output row
// =====================================================================
__global__ __launch_bounds__(256)
void k2_select(const float* __restrict__ x, const float* __restrict__ ca,
               float* __restrict__ out)
{
    __shared__ float glo[512];
    __shared__ float score[256];
    __shared__ float nscore[128];
    __shared__ float nw[128];
    __shared__ int   nonidx[128];

    const int b    = blockIdx.x;
    const int tid  = threadIdx.x;
    const int warp = tid >> 5;
    const int lane = tid & 31;
    const float* __restrict__ xb = x + (size_t)b * NTOK * DIMV;
    float* __restrict__ ob = out + (size_t)b * OUTROWS * DIMV;

    glo[tid]       = g_glo[b * DIMV + tid];
    glo[tid + 256] = g_glo[b * DIMV + tid + 256];
    __syncthreads();

    {
        const float4* glo4 = reinterpret_cast<const float4*>(glo);
        #pragma unroll 1
        for (int r = 0; r < 32; r++) {
            const int t = warp * 32 + r;
            const float4* row = reinterpret_cast<const float4*>(xb + t * DIMV);
            float d = 0.0f;
            #pragma unroll
            for (int q = 0; q < 4; q++) {
                float4 v = row[lane + 32 * q];
                float4 gg = glo4[lane + 32 * q];
                d += v.x * gg.x + v.y * gg.y + v.z * gg.z + v.w * gg.w;
            }
            #pragma unroll
            for (int off = 16; off; off >>= 1) d += __shfl_down_sync(0xffffffffu, d, off);
            if (lane == 0) {
                float nr = sqrtf(g_rowsumsq[b * NTOK + t]);
                score[t] = d / fmaxf(nr, 1e-12f) + ca[(size_t)b * NTOK + t];
            }
        }
    }
    __syncthreads();

    // rank partition (stable argsort of -score semantics)
    {
        const float sc = score[tid];
        int rank = 0;
        #pragma unroll 4
        for (int j = 0; j < NTOK; j++) {
            float sj = score[j];
            rank += (sj > sc) || (sj == sc && j < tid);
        }
        const float rs = g_rowsum[b * NTOK + tid];
        const float rq = g_rowsumsq[b * NTOK + tid];
        const float mu  = rs * (1.0f / 512.0f);
        const float var = rq * (1.0f / 512.0f) - mu * mu;
        if (rank < NKEEP) {
            g_selidx[b * NKEEP + rank] = tid;
            g_mu[b * NKEEP + rank]     = mu;
            g_rinv[b * NKEEP + rank]   = rsqrtf(var + 1e-5f);
        } else {
            nonidx[rank - NKEEP] = tid;
            nscore[rank - NKEEP] = sc;
        }
    }
    __syncthreads();

    if (warp == 0) {
        float v0 = nscore[lane], v1 = nscore[lane + 32],
              v2 = nscore[lane + 64], v3 = nscore[lane + 96];
        float m = fmaxf(fmaxf(v0, v1), fmaxf(v2, v3));
        #pragma unroll
        for (int off = 16; off; off >>= 1) m = fmaxf(m, __shfl_xor_sync(0xffffffffu, m, off));
        float e0 = expf(v0 - m), e1 = expf(v1 - m), e2 = expf(v2 - m), e3 = expf(v3 - m);
        float su = e0 + e1 + e2 + e3;
        #pragma unroll
        for (int off = 16; off; off >>= 1) su += __shfl_xor_sync(0xffffffffu, su, off);
        const float inv = 1.0f / su;
        nw[lane] = e0 * inv; nw[lane + 32] = e1 * inv;
        nw[lane + 64] = e2 * inv; nw[lane + 96] = e3 * inv;
    }
    __syncthreads();

    // extra row (out row 51), 2 cols/thread, depth-2 prefetch
    {
        float acc1 = 0.0f, acc2 = 0.0f;
        int i0 = nonidx[0], i1 = nonidx[1];
        float a0 = xb[(size_t)i0 * DIMV + tid],  b0 = xb[(size_t)i0 * DIMV + tid + 256];
        float a1 = xb[(size_t)i1 * DIMV + tid],  b1v = xb[(size_t)i1 * DIMV + tid + 256];
        #pragma unroll 2
        for (int k = 0; k < 128; k++) {
            float an = 0.0f, bn = 0.0f;
            if (k + 2 < 128) {
                int in = nonidx[k + 2];
                an = xb[(size_t)in * DIMV + tid];
                bn = xb[(size_t)in * DIMV + tid + 256];
            }
            float w = nw[k];
            acc1 += w * a0; acc2 += w * b0;
            a0 = a1; b0 = b1v; a1 = an; b1v = bn;
        }
        ob[51 * DIMV + tid]       = acc1;
        ob[51 * DIMV + tid + 256] = acc2;
    }
}

// =====================================================================
// K3: GEMM1(+LN+gelu) -> GEMM2 -> softmax -> aggr
// =====================================================================
#define ATS 129   // A_T row stride (floats); 129 % 32 == 1 -> conflict-free lane reads

struct __align__(16) SmemK3 {
    float A_T[32 * ATS];     // transposed LN(sel) tile [dk][t]
    float Bt[32 * 104];      // W1 tile, cols 102/103 zero
    float H[128 * 104];      // gelu output; cols 52..103 reused for softmaxed w
    float W2s[HID * 52];     // W2 padded, col 51 = 0
    float g[512];
    float bln[512];
    float mu[128];
    float rinv[128];
    float b1p[104];
    float b2s[52];
    int   selidx[128];
};

__global__ __launch_bounds__(256, 2)
void k3_mlp(const float* __restrict__ x,
            const float* __restrict__ lng, const float* __restrict__ lnb,
            const float* __restrict__ W1, const float* __restrict__ b1,
            const float* __restrict__ W2, const float* __restrict__ b2,
            const float* __restrict__ scale, float* __restrict__ out)
{
    extern __shared__ char smem_raw[];
    SmemK3& s = *reinterpret_cast<SmemK3*>(smem_raw);

    const int b    = blockIdx.x;
    const int tid  = threadIdx.x;
    const int warp = tid >> 5;
    const int lane = tid & 31;
    const float* __restrict__ xb = x + (size_t)b * NTOK * DIMV;
    float* __restrict__ ob = out + (size_t)b * OUTROWS * DIMV;

    // ---- load constants/selection ----
    s.g[tid]         = lng[tid];
    s.g[tid + 256]   = lng[tid + 256];
    s.bln[tid]       = lnb[tid];
    s.bln[tid + 256] = lnb[tid + 256];
    if (tid < 104) s.b1p[tid] = (tid < HID) ? b1[tid] : 0.0f;
    if (tid < KP)  s.b2s[tid] = b2[tid];
    if (tid < 128) {
        s.selidx[tid] = g_selidx[b * NKEEP + tid];
        s.mu[tid]     = g_mu[b * NKEEP + tid];
        s.rinv[tid]   = g_rinv[b * NKEEP + tid];
    }
    if (tid < 64) s.Bt[(tid >> 1) * 104 + 102 + (tid & 1)] = 0.0f;   // Bt pad cols
    if (tid < HID) s.W2s[tid * 52 + 51] = 0.0f;                      // W2 pad col
    #pragma unroll
    for (int j = tid; j < HID * KP; j += 256)
        s.W2s[(j / KP) * 52 + (j % KP)] = W2[j];
    __syncthreads();

    // ---- GEMM1: H = gelu( LN(sel) @ W1 + b1 ) ----
    // warp w: row-group rg = w>>2 (rows rg*64+lane, +32), col-group cg = w&3 (cols cg*26..+25)
    const int rg = warp >> 2;
    const int cg = warp & 3;
    const int r0 = rg * 64 + lane;
    const int c0 = cg * 26;

    ull acc0[13], acc1[13];
    #pragma unroll
    for (int i = 0; i < 13; i++) { acc0[i] = 0ull; acc1[i] = 0ull; }

    const int tA   = tid >> 1;          // row this thread stages
    const int dv0  = (tid & 1) * 16;    // dim-half within 32-chunk

    #pragma unroll 1
    for (int kt = 0; kt < 16; kt++) {
        const int d0 = kt * 32;
        // stage A_T[dkloc][t] with LN applied (conflict-free STS pattern)
        {
            const int rowi = s.selidx[tA];
            const float muv = s.mu[tA], ri = s.rinv[tA];
            const float4* src = reinterpret_cast<const float4*>(xb + (size_t)rowi * DIMV + d0 + dv0);
            #pragma unroll
            for (int q = 0; q < 4; q++) {
                float4 v = src[q];
                const int dd = d0 + dv0 + 4 * q;
                float y0 = (v.x - muv) * ri * s.g[dd + 0] + s.bln[dd + 0];
                float y1 = (v.y - muv) * ri * s.g[dd + 1] + s.bln[dd + 1];
                float y2 = (v.z - muv) * ri * s.g[dd + 2] + s.bln[dd + 2];
                float y3 = (v.w - muv) * ri * s.g[dd + 3] + s.bln[dd + 3];
                const int dl = dv0 + 4 * q;
                s.A_T[(dl + 0) * ATS + tA] = y0;
                s.A_T[(dl + 1) * ATS + tA] = y1;
                s.A_T[(dl + 2) * ATS + tA] = y2;
                s.A_T[(dl + 3) * ATS + tA] = y3;
            }
        }
        // stage Bt = W1[d0..d0+31][:] via float2
        #pragma unroll
        for (int jj = tid; jj < 32 * 51; jj += 256) {
            const int dk = jj / 51;
            const int c2 = jj - dk * 51;
            float2 v = *reinterpret_cast<const float2*>(W1 + (size_t)(d0 + dk) * HID + 2 * c2);
            *reinterpret_cast<float2*>(&s.Bt[dk * 104 + 2 * c2]) = v;
        }
        __syncthreads();

        #pragma unroll 2
        for (int dk = 0; dk < 32; dk++) {
            const float a0 = s.A_T[dk * ATS + r0];
            const float a1 = s.A_T[dk * ATS + r0 + 32];
            const ull a2_0 = pack2(a0, a0);
            const ull a2_1 = pack2(a1, a1);
            const ull* bp = reinterpret_cast<const ull*>(&s.Bt[dk * 104 + c0]);
            #pragma unroll
            for (int i = 0; i < 13; i++) {
                const ull bv = bp[i];
                acc0[i] = ffma2(a2_0, bv, acc0[i]);
                acc1[i] = ffma2(a2_1, bv, acc1[i]);
            }
        }
        __syncthreads();
    }
    // write H = gelu(acc + b1)
    {
        #pragma unroll
        for (int i = 0; i < 13; i++) {
            const int c = c0 + 2 * i;
            float2 p0 = unpack2(acc0[i]);
            float2 p1 = unpack2(acc1[i]);
            float b0 = s.b1p[c], b1v = s.b1p[c + 1];
            *reinterpret_cast<float2*>(&s.H[r0 * 104 + c]) =
                make_float2(gelu_exact(p0.x + b0), gelu_exact(p0.y + b1v));
            *reinterpret_cast<float2*>(&s.H[(r0 + 32) * 104 + c]) =
                make_float2(gelu_exact(p1.x + b0), gelu_exact(p1.y + b1v));
        }
    }
    __syncthreads();

    // ---- GEMM2: w = (H @ W2 + b2) * scale -> stored at H[t][52..103] ----
    {
        const int t  = tid >> 1;
        const int cc0 = (tid & 1) * 26;
        ull accw[13];
        #pragma unroll
        for (int i = 0; i < 13; i++) accw[i] = 0ull;
        const float* hrow = &s.H[t * 104];
        #pragma unroll 2
        for (int k = 0; k < HID; k++) {
            const float h = hrow[k];
            const ull h2 = pack2(h, h);
            const ull* wr = reinterpret_cast<const ull*>(&s.W2s[k * 52 + cc0]);
            #pragma unroll
            for (int i = 0; i < 13; i++) accw[i] = ffma2(h2, wr[i], accw[i]);
        }
        const float sv = scale[0];
        __syncwarp();  // partner thread in same warp must finish reading hrow
        float* wrow = &s.H[t * 104 + 52];
        #pragma unroll
        for (int i = 0; i < 13; i++) {
            float2 v = unpack2(accw[i]);
            const int c = cc0 + 2 * i;
            float o0 = (v.x + s.b2s[c]) * sv;
            float o1 = (c + 1 < KP) ? (v.y + s.b2s[c + 1]) * sv : 0.0f;
            *reinterpret_cast<float2*>(&wrow[c]) = make_float2(o0, o1);
        }
    }
    __syncthreads();

    // ---- softmax over 128 tokens per weight column ----
    for (int c = warp; c < KP; c += 8) {
        const int base = 52 + c;
        float v0 = s.H[(lane) * 104 + base],      v1 = s.H[(lane + 32) * 104 + base],
              v2 = s.H[(lane + 64) * 104 + base], v3 = s.H[(lane + 96) * 104 + base];
        float m = fmaxf(fmaxf(v0, v1), fmaxf(v2, v3));
        #pragma unroll
        for (int off = 16; off; off >>= 1) m = fmaxf(m, __shfl_xor_sync(0xffffffffu, m, off));
        float e0 = expf(v0 - m), e1 = expf(v1 - m), e2 = expf(v2 - m), e3 = expf(v3 - m);
        float su = e0 + e1 + e2 + e3;
        #pragma unroll
        for (int off = 16; off; off >>= 1) su += __shfl_xor_sync(0xffffffffu, su, off);
        const float inv = 1.0f / su;
        s.H[(lane) * 104 + base]      = e0 * inv;
        s.H[(lane + 32) * 104 + base] = e1 * inv;
        s.H[(lane + 64) * 104 + base] = e2 * inv;
        s.H[(lane + 96) * 104 + base] = e3 * inv;
    }
    __syncthreads();

    // ---- aggr: out[p][c] = sum_k w[k][p] * sel[k][c] ----
    #pragma unroll 1
    for (int pass = 0; pass < 2; pass++) {
        const int c = tid + pass * 256;
        ull acc2[26];
        #pragma unroll
        for (int p = 0; p < 26; p++) acc2[p] = 0ull;
        float xv0 = xb[(size_t)s.selidx[0] * DIMV + c];
        float xv1 = xb[(size_t)s.selidx[1] * DIMV + c];
        #pragma unroll 2
        for (int k = 0; k < 128; k++) {
            float nxt = (k + 2 < 128) ? xb[(size_t)s.selidx[k + 2] * DIMV + c] : 0.0f;
            const ull x2 = pack2(xv0, xv0);
            const ull* wr = reinterpret_cast<const ull*>(&s.H[k * 104 + 52]);
            #pragma unroll
            for (int p = 0; p < 26; p++) acc2[p] = ffma2(x2, wr[p], acc2[p]);
            xv0 = xv1; xv1 = nxt;
        }
        #pragma unroll
        for (int p = 0; p < 26; p++) {
            float2 v = unpack2(acc2[p]);
            ob[(2 * p) * DIMV + c] = v.x;
            if (2 * p + 1 < KP) ob[(2 * p + 1) * DIMV + c] = v.y;
        }
    }
}

extern "C" void kernel_launch(void* const* d_in, const int* in_sizes, int n_in,
                              void* d_out, int out_size) {
    (void)in_sizes; (void)n_in; (void)out_size;
    const float* x    = (const float*)d_in[0];
    const float* ca   = (const float*)d_in[1];
    const float* lng  = (const float*)d_in[2];
    const float* lnb  = (const float*)d_in[3];
    const float* W1   = (const float*)d_in[4];
    const float* b1   = (const float*)d_in[5];
    const float* W2   = (const float*)d_in[6];
    const float* b2   = (const float*)d_in[7];
    const float* sc   = (const float*)d_in[8];
    float* out = (float*)d_out;

    static_assert(sizeof(SmemK3) <= 113 * 1024, "K3 smem too big for 2 CTAs/SM");
    cudaFuncSetAttribute(k3_mlp, cudaFuncAttributeMaxDynamicSharedMemorySize,
                         (int)sizeof(SmemK3));

    k1_stats<<<NB, 256>>>(x);
    k2_select<<<NB, 256>>>(x, ca, out);
    k3_mlp<<<NB, 256, sizeof(SmemK3)>>>(x, lng, lnb, W1, b1, W2, b2, sc, out);
}